// round 2
// baseline (speedup 1.0000x reference)
#include <cuda_runtime.h>
#include <stdint.h>
#include <math.h>

#define F_IN  256
#define HID   128
#define C_OUT 40
#define NMAX  100000

// Scratch (allocation-free rule: __device__ globals)
__device__ float g_h1[(size_t)NMAX * HID];    // x @ W1
__device__ float g_agg1[(size_t)NMAX * HID];  // scatter result layer 1 (+b1)
__device__ float g_h2[(size_t)NMAX * C_OUT];  // relu(agg1) @ W2

// ---------------------------------------------------------------------------
// GEMM1: H1[M,128] = X[M,256] @ W1[256,128]   (classic 128x128x16 SGEMM tile)
// ---------------------------------------------------------------------------
__global__ __launch_bounds__(256) void gemm1_kernel(
    const float* __restrict__ X, const float* __restrict__ W, int M) {
  __shared__ float As[16][128];  // transposed A tile
  __shared__ float Bs[16][128];
  const int t = threadIdx.x;
  const int row0 = blockIdx.x * 128;
  const int tx = t & 15;   // 0..15 -> 8 cols each
  const int ty = t >> 4;   // 0..15 -> 8 rows each

  float acc[8][8];
#pragma unroll
  for (int i = 0; i < 8; i++)
#pragma unroll
    for (int j = 0; j < 8; j++) acc[i][j] = 0.f;

  for (int k0 = 0; k0 < F_IN; k0 += 16) {
    // Load A tile: 128 rows x 16 cols = 512 float4
#pragma unroll
    for (int i = 0; i < 2; i++) {
      int id = t + i * 256;
      int r = id >> 2;      // 0..127
      int c4 = id & 3;      // 0..3
      float4 v = make_float4(0.f, 0.f, 0.f, 0.f);
      int grow = row0 + r;
      if (grow < M) v = *(const float4*)(X + (size_t)grow * F_IN + k0 + c4 * 4);
      As[c4 * 4 + 0][r] = v.x;
      As[c4 * 4 + 1][r] = v.y;
      As[c4 * 4 + 2][r] = v.z;
      As[c4 * 4 + 3][r] = v.w;
    }
    // Load B tile: 16 rows x 128 cols = 512 float4
#pragma unroll
    for (int i = 0; i < 2; i++) {
      int id = t + i * 256;
      int r = id >> 5;      // 0..15
      int c4 = id & 31;     // 0..31
      *(float4*)(&Bs[r][c4 * 4]) = *(const float4*)(W + (size_t)(k0 + r) * HID + c4 * 4);
    }
    __syncthreads();
#pragma unroll
    for (int k = 0; k < 16; k++) {
      float a[8], b[8];
#pragma unroll
      for (int i = 0; i < 8; i++) a[i] = As[k][ty * 8 + i];
#pragma unroll
      for (int j = 0; j < 8; j++) b[j] = Bs[k][tx * 8 + j];
#pragma unroll
      for (int i = 0; i < 8; i++)
#pragma unroll
        for (int j = 0; j < 8; j++) acc[i][j] += a[i] * b[j];
    }
    __syncthreads();
  }
#pragma unroll
  for (int i = 0; i < 8; i++) {
    int grow = row0 + ty * 8 + i;
    if (grow < M) {
      float* dst = g_h1 + (size_t)grow * HID + tx * 8;
      *(float4*)(dst + 0) = make_float4(acc[i][0], acc[i][1], acc[i][2], acc[i][3]);
      *(float4*)(dst + 4) = make_float4(acc[i][4], acc[i][5], acc[i][6], acc[i][7]);
    }
  }
}

// ---------------------------------------------------------------------------
// Init accumulators with bias
// ---------------------------------------------------------------------------
__global__ void init_agg1_kernel(const float* __restrict__ b1, long long total) {
  long long i = (long long)blockIdx.x * blockDim.x + threadIdx.x;
  if (i < total) g_agg1[i] = __ldg(b1 + (int)(i & (HID - 1)));
}

__global__ void init_out_kernel(float* __restrict__ out, const float* __restrict__ b2,
                                long long total) {
  long long i = (long long)blockIdx.x * blockDim.x + threadIdx.x;
  if (i < total) out[i] = __ldg(b2 + (int)(i % C_OUT));
}

// ---------------------------------------------------------------------------
// Scatter layer 1: one warp per edge, 128 floats = 32 lanes x float4
// agg1[dst] += w * h1[src]
// edge_index is INT32 (jax default x64-disabled): ei[0:E]=src, ei[E:2E]=dst
// ---------------------------------------------------------------------------
__global__ __launch_bounds__(256) void scatter1_kernel(
    const int* __restrict__ ei, const float* __restrict__ ew, long long E) {
  long long tid = (long long)blockIdx.x * blockDim.x + threadIdx.x;
  long long e = tid >> 5;
  if (e >= E) return;
  int lane = threadIdx.x & 31;
  int src = __ldg(ei + e);
  int dst = __ldg(ei + E + e);
  float w = __ldg(ew + e);
  float4 v = *(const float4*)(g_h1 + (size_t)src * HID + lane * 4);
  float* p = g_agg1 + (size_t)dst * HID + lane * 4;
  asm volatile("red.global.add.v4.f32 [%0], {%1,%2,%3,%4};"
               :: "l"(p), "f"(v.x * w), "f"(v.y * w), "f"(v.z * w), "f"(v.w * w)
               : "memory");
}

// ---------------------------------------------------------------------------
// GEMM2: H2[M,40] = relu(agg1)[M,128] @ W2[128,40]
// Block: 32 rows, 256 threads; W2 fully in smem.
// Warp w handles rows [4w,4w+4); lane handles col=lane (+ col=lane+32 for lane<8)
// ---------------------------------------------------------------------------
__global__ __launch_bounds__(256) void gemm2_kernel(
    const float* __restrict__ W, int M) {
  __shared__ float Hs[32][HID];
  __shared__ float Ws[HID][C_OUT];
  const int t = threadIdx.x;
  const int row0 = blockIdx.x * 32;

  for (int i = t; i < HID * C_OUT; i += 256) Ws[i / C_OUT][i % C_OUT] = __ldg(W + i);
  for (int i = t; i < 32 * 32; i += 256) {
    int r = i >> 5, c4 = i & 31;
    int grow = row0 + r;
    float4 v = make_float4(0.f, 0.f, 0.f, 0.f);
    if (grow < M) v = *(const float4*)(g_agg1 + (size_t)grow * HID + c4 * 4);
    v.x = fmaxf(v.x, 0.f); v.y = fmaxf(v.y, 0.f);
    v.z = fmaxf(v.z, 0.f); v.w = fmaxf(v.w, 0.f);
    *(float4*)(&Hs[r][c4 * 4]) = v;
  }
  __syncthreads();

  const int warp = t >> 5, lane = t & 31;
  const int rbase = warp * 4;
  const bool has2 = lane < 8;
  float acc[4][2];
#pragma unroll
  for (int r = 0; r < 4; r++) { acc[r][0] = 0.f; acc[r][1] = 0.f; }

  for (int k = 0; k < HID; k += 4) {
    float hk[4][4];
#pragma unroll
    for (int r = 0; r < 4; r++) {
      float4 h4 = *(const float4*)(&Hs[rbase + r][k]);
      hk[r][0] = h4.x; hk[r][1] = h4.y; hk[r][2] = h4.z; hk[r][3] = h4.w;
    }
#pragma unroll
    for (int kk = 0; kk < 4; kk++) {
      float w0 = Ws[k + kk][lane];
      float w1 = has2 ? Ws[k + kk][lane + 32] : 0.f;
#pragma unroll
      for (int r = 0; r < 4; r++) {
        acc[r][0] += hk[r][kk] * w0;
        acc[r][1] += hk[r][kk] * w1;
      }
    }
  }
#pragma unroll
  for (int r = 0; r < 4; r++) {
    int grow = row0 + rbase + r;
    if (grow < M) {
      g_h2[(size_t)grow * C_OUT + lane] = acc[r][0];
      if (has2) g_h2[(size_t)grow * C_OUT + lane + 32] = acc[r][1];
    }
  }
}

// ---------------------------------------------------------------------------
// Scatter layer 2: 10 float4-chunks per edge (40 floats)
// out[dst] += w * h2[src]
// ---------------------------------------------------------------------------
__global__ __launch_bounds__(256) void scatter2_kernel(
    const int* __restrict__ ei, const float* __restrict__ ew,
    float* __restrict__ out, long long E) {
  long long tid = (long long)blockIdx.x * blockDim.x + threadIdx.x;
  long long e = tid / 10;
  int c = (int)(tid - e * 10);
  if (e >= E) return;
  int src = __ldg(ei + e);
  int dst = __ldg(ei + E + e);
  float w = __ldg(ew + e);
  float4 v = *(const float4*)(g_h2 + (size_t)src * C_OUT + c * 4);
  float* p = out + (size_t)dst * C_OUT + c * 4;
  asm volatile("red.global.add.v4.f32 [%0], {%1,%2,%3,%4};"
               :: "l"(p), "f"(v.x * w), "f"(v.y * w), "f"(v.z * w), "f"(v.w * w)
               : "memory");
}

// ---------------------------------------------------------------------------
// log_softmax in place over 40 classes; one warp per row
// ---------------------------------------------------------------------------
__global__ __launch_bounds__(256) void logsoftmax_kernel(float* __restrict__ out, int M) {
  int row = blockIdx.x * 8 + (threadIdx.x >> 5);
  int lane = threadIdx.x & 31;
  if (row >= M) return;
  float* p = out + (size_t)row * C_OUT;
  float v0 = p[lane];
  float v1 = (lane < 8) ? p[lane + 32] : -INFINITY;
  float m = fmaxf(v0, v1);
#pragma unroll
  for (int o = 16; o; o >>= 1) m = fmaxf(m, __shfl_xor_sync(0xffffffffu, m, o));
  float s = expf(v0 - m) + ((lane < 8) ? expf(v1 - m) : 0.f);
#pragma unroll
  for (int o = 16; o; o >>= 1) s += __shfl_xor_sync(0xffffffffu, s, o);
  float lse = m + logf(s);
  p[lane] = v0 - lse;
  if (lane < 8) p[lane + 32] = v1 - lse;
}

// ---------------------------------------------------------------------------
extern "C" void kernel_launch(void* const* d_in, const int* in_sizes, int n_in,
                              void* d_out, int out_size) {
  const float* x        = (const float*)d_in[0];
  const int*   ei       = (const int*)d_in[1];   // int32! (jax x64 disabled)
  const float* ew       = (const float*)d_in[2];
  const float* W1       = (const float*)d_in[3];
  const float* b1       = (const float*)d_in[4];
  const float* W2       = (const float*)d_in[5];
  const float* b2       = (const float*)d_in[6];
  float* out            = (float*)d_out;

  const int M = in_sizes[0] / F_IN;
  const long long E = in_sizes[2];   // edge_weight element count = E

  // 1) H1 = x @ W1
  gemm1_kernel<<<(M + 127) / 128, 256>>>(x, W1, M);

  // 2) agg1 = b1 (broadcast)
  {
    long long total = (long long)M * HID;
    init_agg1_kernel<<<(unsigned)((total + 255) / 256), 256>>>(b1, total);
  }

  // 3) agg1[dst] += w * H1[src]   (one warp per edge)
  {
    long long threads = E * 32;
    scatter1_kernel<<<(unsigned)((threads + 255) / 256), 256>>>(ei, ew, E);
  }

  // 4) H2 = relu(agg1) @ W2
  gemm2_kernel<<<(M + 31) / 32, 256>>>(W2, M);

  // 5) out = b2 (broadcast)
  {
    long long total = (long long)M * C_OUT;
    init_out_kernel<<<(unsigned)((total + 255) / 256), 256>>>(out, b2, total);
  }

  // 6) out[dst] += w * H2[src]    (10 float4-chunks per edge)
  {
    long long threads = E * 10;
    scatter2_kernel<<<(unsigned)((threads + 255) / 256), 256>>>(ei, ew, out, E);
  }

  // 7) log_softmax in place
  logsoftmax_kernel<<<(M + 7) / 8, 256>>>(out, M);
}

// round 3
// speedup vs baseline: 1.1436x; 1.1436x over previous
#include <cuda_runtime.h>
#include <stdint.h>
#include <math.h>

#define F_IN  256
#define HID   128
#define C_OUT 40
#define NMAX  100000

// Scratch (allocation-free rule: __device__ globals)
__device__ float g_h1[(size_t)NMAX * HID];    // x @ W1
__device__ float g_agg1[(size_t)NMAX * HID];  // scatter result layer 1 (+b1)
__device__ float g_h2[(size_t)NMAX * C_OUT];  // relu(agg1) @ W2

// ---------------------------------------------------------------------------
// helpers
// ---------------------------------------------------------------------------
__device__ __forceinline__ uint32_t f2tf32(float x) {
  uint32_t r;
  asm("cvt.rna.tf32.f32 %0, %1;" : "=r"(r) : "f"(x));
  return r;
}

__device__ __forceinline__ void mma_tf32(
    float* d, const uint32_t* a, const uint32_t* b, const float* c) {
  asm volatile(
      "mma.sync.aligned.m16n8k8.row.col.f32.tf32.tf32.f32 "
      "{%0,%1,%2,%3}, {%4,%5,%6,%7}, {%8,%9}, {%10,%11,%12,%13};"
      : "=f"(d[0]), "=f"(d[1]), "=f"(d[2]), "=f"(d[3])
      : "r"(a[0]), "r"(a[1]), "r"(a[2]), "r"(a[3]),
        "r"(b[0]), "r"(b[1]),
        "f"(c[0]), "f"(c[1]), "f"(c[2]), "f"(c[3]));
}

// ---------------------------------------------------------------------------
// GEMM1: H1[M,128] = X[M,256] @ W1[256,128], tf32 tensor-core path.
// Block: 256 threads (8 warps as 4(m) x 2(n)); block tile 128x128, BK=32.
// Warp tile 32x64 = 2(m16) x 8(n8) mma tiles.
// ---------------------------------------------------------------------------
#define G1_BK 32
#define G1_PAD 4
__global__ __launch_bounds__(256) void gemm1_kernel(
    const float* __restrict__ X, const float* __restrict__ W, int M) {
  __shared__ uint32_t As[G1_BK][128 + G1_PAD];  // [k][m], tf32 bits
  __shared__ uint32_t Bs[G1_BK][HID + G1_PAD];  // [k][n], tf32 bits

  const int t = threadIdx.x;
  const int row0 = blockIdx.x * 128;
  const int warp = t >> 5;
  const int lane = t & 31;
  const int g  = lane >> 2;   // group id 0..7
  const int tg = lane & 3;    // thread-in-group 0..3
  const int m_base = (warp & 3) * 32;
  const int n_base = (warp >> 2) * 64;

  float acc[2][8][4];
#pragma unroll
  for (int mt = 0; mt < 2; mt++)
#pragma unroll
    for (int nt = 0; nt < 8; nt++)
#pragma unroll
      for (int i = 0; i < 4; i++) acc[mt][nt][i] = 0.f;

  for (int k0 = 0; k0 < F_IN; k0 += G1_BK) {
    // Load A tile 128 rows x 32 cols -> As[k][m]  (1024 float4, 4 per thread)
#pragma unroll
    for (int i = 0; i < 4; i++) {
      int id = t + i * 256;
      int r = id >> 3;      // 0..127
      int c4 = id & 7;      // 0..7
      float4 v = make_float4(0.f, 0.f, 0.f, 0.f);
      int grow = row0 + r;
      if (grow < M) v = *(const float4*)(X + (size_t)grow * F_IN + k0 + c4 * 4);
      As[c4 * 4 + 0][r] = f2tf32(v.x);
      As[c4 * 4 + 1][r] = f2tf32(v.y);
      As[c4 * 4 + 2][r] = f2tf32(v.z);
      As[c4 * 4 + 3][r] = f2tf32(v.w);
    }
    // Load B tile 32 rows x 128 cols -> Bs[k][n]
#pragma unroll
    for (int i = 0; i < 4; i++) {
      int id = t + i * 256;
      int r = id >> 5;      // 0..31
      int c4 = id & 31;     // 0..31
      float4 v = *(const float4*)(W + (size_t)(k0 + r) * HID + c4 * 4);
      Bs[r][c4 * 4 + 0] = f2tf32(v.x);
      Bs[r][c4 * 4 + 1] = f2tf32(v.y);
      Bs[r][c4 * 4 + 2] = f2tf32(v.z);
      Bs[r][c4 * 4 + 3] = f2tf32(v.w);
    }
    __syncthreads();

#pragma unroll
    for (int kk = 0; kk < G1_BK / 8; kk++) {
      uint32_t a[2][4];
#pragma unroll
      for (int mt = 0; mt < 2; mt++) {
        int mr = m_base + mt * 16;
        a[mt][0] = As[kk * 8 + tg    ][mr + g    ];
        a[mt][1] = As[kk * 8 + tg    ][mr + g + 8];
        a[mt][2] = As[kk * 8 + tg + 4][mr + g    ];
        a[mt][3] = As[kk * 8 + tg + 4][mr + g + 8];
      }
#pragma unroll
      for (int nt = 0; nt < 8; nt++) {
        uint32_t b[2];
        b[0] = Bs[kk * 8 + tg    ][n_base + nt * 8 + g];
        b[1] = Bs[kk * 8 + tg + 4][n_base + nt * 8 + g];
        mma_tf32(acc[0][nt], a[0], b, acc[0][nt]);
        mma_tf32(acc[1][nt], a[1], b, acc[1][nt]);
      }
    }
    __syncthreads();
  }

  // Epilogue: c0,c1 -> (row g, col 2tg..2tg+1); c2,c3 -> (row g+8)
#pragma unroll
  for (int mt = 0; mt < 2; mt++) {
    int r1 = row0 + m_base + mt * 16 + g;
    int r2 = r1 + 8;
#pragma unroll
    for (int nt = 0; nt < 8; nt++) {
      int col = n_base + nt * 8 + tg * 2;
      if (r1 < M) *(float2*)(g_h1 + (size_t)r1 * HID + col) =
          make_float2(acc[mt][nt][0], acc[mt][nt][1]);
      if (r2 < M) *(float2*)(g_h1 + (size_t)r2 * HID + col) =
          make_float2(acc[mt][nt][2], acc[mt][nt][3]);
    }
  }
}

// ---------------------------------------------------------------------------
// Init accumulators with bias
// ---------------------------------------------------------------------------
__global__ void init_agg1_kernel(const float* __restrict__ b1, long long total) {
  long long i = (long long)blockIdx.x * blockDim.x + threadIdx.x;
  if (i < total) g_agg1[i] = __ldg(b1 + (int)(i & (HID - 1)));
}

__global__ void init_out_kernel(float* __restrict__ out, const float* __restrict__ b2,
                                long long total) {
  long long i = (long long)blockIdx.x * blockDim.x + threadIdx.x;
  if (i < total) out[i] = __ldg(b2 + (int)(i % C_OUT));
}

// ---------------------------------------------------------------------------
// Scatter layer 1: one warp per edge; agg1[dst] += w * h1[src]
// edge_index is int32: ei[0:E]=src, ei[E:2E]=dst
// ---------------------------------------------------------------------------
__global__ __launch_bounds__(256) void scatter1_kernel(
    const int* __restrict__ ei, const float* __restrict__ ew, long long E) {
  long long tid = (long long)blockIdx.x * blockDim.x + threadIdx.x;
  long long e = tid >> 5;
  if (e >= E) return;
  int lane = threadIdx.x & 31;
  int src = __ldg(ei + e);
  int dst = __ldg(ei + E + e);
  float w = __ldg(ew + e);
  float4 v = *(const float4*)(g_h1 + (size_t)src * HID + lane * 4);
  float* p = g_agg1 + (size_t)dst * HID + lane * 4;
  asm volatile("red.global.add.v4.f32 [%0], {%1,%2,%3,%4};"
               :: "l"(p), "f"(v.x * w), "f"(v.y * w), "f"(v.z * w), "f"(v.w * w)
               : "memory");
}

// ---------------------------------------------------------------------------
// GEMM2: H2[M,40] = relu(agg1)[M,128] @ W2[128,40]
// 128-thread blocks, 32 rows/block, 8 rows per warp (halved Ws LDS per FMA).
// ---------------------------------------------------------------------------
__global__ __launch_bounds__(128) void gemm2_kernel(
    const float* __restrict__ W, int M) {
  __shared__ float Hs[32][HID];
  __shared__ float Ws[HID][C_OUT];
  const int t = threadIdx.x;
  const int row0 = blockIdx.x * 32;

  for (int i = t; i < HID * C_OUT; i += 128) Ws[i / C_OUT][i % C_OUT] = __ldg(W + i);
  for (int i = t; i < 32 * 32; i += 128) {
    int r = i >> 5, c4 = i & 31;
    int grow = row0 + r;
    float4 v = make_float4(0.f, 0.f, 0.f, 0.f);
    if (grow < M) v = *(const float4*)(g_agg1 + (size_t)grow * HID + c4 * 4);
    v.x = fmaxf(v.x, 0.f); v.y = fmaxf(v.y, 0.f);
    v.z = fmaxf(v.z, 0.f); v.w = fmaxf(v.w, 0.f);
    *(float4*)(&Hs[r][c4 * 4]) = v;
  }
  __syncthreads();

  const int warp = t >> 5, lane = t & 31;
  const int rbase = warp * 8;
  const bool has2 = lane < 8;
  float acc[8][2];
#pragma unroll
  for (int r = 0; r < 8; r++) { acc[r][0] = 0.f; acc[r][1] = 0.f; }

  for (int k = 0; k < HID; k += 4) {
    float hk[8][4];
#pragma unroll
    for (int r = 0; r < 8; r++) {
      float4 h4 = *(const float4*)(&Hs[rbase + r][k]);
      hk[r][0] = h4.x; hk[r][1] = h4.y; hk[r][2] = h4.z; hk[r][3] = h4.w;
    }
#pragma unroll
    for (int kk = 0; kk < 4; kk++) {
      float w0 = Ws[k + kk][lane];
      float w1 = has2 ? Ws[k + kk][lane + 32] : 0.f;
#pragma unroll
      for (int r = 0; r < 8; r++) {
        acc[r][0] += hk[r][kk] * w0;
        acc[r][1] += hk[r][kk] * w1;
      }
    }
  }
#pragma unroll
  for (int r = 0; r < 8; r++) {
    int grow = row0 + rbase + r;
    if (grow < M) {
      g_h2[(size_t)grow * C_OUT + lane] = acc[r][0];
      if (has2) g_h2[(size_t)grow * C_OUT + lane + 32] = acc[r][1];
    }
  }
}

// ---------------------------------------------------------------------------
// Scatter layer 2: 10 float4-chunks per edge (40 floats)
// ---------------------------------------------------------------------------
__global__ __launch_bounds__(256) void scatter2_kernel(
    const int* __restrict__ ei, const float* __restrict__ ew,
    float* __restrict__ out, long long E) {
  long long tid = (long long)blockIdx.x * blockDim.x + threadIdx.x;
  long long e = tid / 10;
  int c = (int)(tid - e * 10);
  if (e >= E) return;
  int src = __ldg(ei + e);
  int dst = __ldg(ei + E + e);
  float w = __ldg(ew + e);
  float4 v = *(const float4*)(g_h2 + (size_t)src * C_OUT + c * 4);
  float* p = out + (size_t)dst * C_OUT + c * 4;
  asm volatile("red.global.add.v4.f32 [%0], {%1,%2,%3,%4};"
               :: "l"(p), "f"(v.x * w), "f"(v.y * w), "f"(v.z * w), "f"(v.w * w)
               : "memory");
}

// ---------------------------------------------------------------------------
// log_softmax in place over 40 classes; one warp per row
// ---------------------------------------------------------------------------
__global__ __launch_bounds__(256) void logsoftmax_kernel(float* __restrict__ out, int M) {
  int row = blockIdx.x * 8 + (threadIdx.x >> 5);
  int lane = threadIdx.x & 31;
  if (row >= M) return;
  float* p = out + (size_t)row * C_OUT;
  float v0 = p[lane];
  float v1 = (lane < 8) ? p[lane + 32] : -INFINITY;
  float m = fmaxf(v0, v1);
#pragma unroll
  for (int o = 16; o; o >>= 1) m = fmaxf(m, __shfl_xor_sync(0xffffffffu, m, o));
  float s = expf(v0 - m) + ((lane < 8) ? expf(v1 - m) : 0.f);
#pragma unroll
  for (int o = 16; o; o >>= 1) s += __shfl_xor_sync(0xffffffffu, s, o);
  float lse = m + logf(s);
  p[lane] = v0 - lse;
  if (lane < 8) p[lane + 32] = v1 - lse;
}

// ---------------------------------------------------------------------------
extern "C" void kernel_launch(void* const* d_in, const int* in_sizes, int n_in,
                              void* d_out, int out_size) {
  const float* x        = (const float*)d_in[0];
  const int*   ei       = (const int*)d_in[1];   // int32
  const float* ew       = (const float*)d_in[2];
  const float* W1       = (const float*)d_in[3];
  const float* b1       = (const float*)d_in[4];
  const float* W2       = (const float*)d_in[5];
  const float* b2       = (const float*)d_in[6];
  float* out            = (float*)d_out;

  const int M = in_sizes[0] / F_IN;
  const long long E = in_sizes[2];

  // 1) H1 = x @ W1  (tf32 tensor cores)
  gemm1_kernel<<<(M + 127) / 128, 256>>>(x, W1, M);

  // 2) agg1 = b1 (broadcast)
  {
    long long total = (long long)M * HID;
    init_agg1_kernel<<<(unsigned)((total + 255) / 256), 256>>>(b1, total);
  }

  // 3) agg1[dst] += w * H1[src]
  {
    long long threads = E * 32;
    scatter1_kernel<<<(unsigned)((threads + 255) / 256), 256>>>(ei, ew, E);
  }

  // 4) H2 = relu(agg1) @ W2
  gemm2_kernel<<<(M + 31) / 32, 128>>>(W2, M);

  // 5) out = b2 (broadcast)
  {
    long long total = (long long)M * C_OUT;
    init_out_kernel<<<(unsigned)((total + 255) / 256), 256>>>(out, b2, total);
  }

  // 6) out[dst] += w * H2[src]
  {
    long long threads = E * 10;
    scatter2_kernel<<<(unsigned)((threads + 255) / 256), 256>>>(ei, ew, out, E);
  }

  // 7) log_softmax in place
  logsoftmax_kernel<<<(M + 7) / 8, 256>>>(out, M);
}

// round 4
// speedup vs baseline: 1.9404x; 1.6968x over previous
#include <cuda_runtime.h>
#include <stdint.h>
#include <math.h>

#define F_IN  256
#define HID   128
#define C_OUT 40
#define NMAX  100000
#define EMAX  3200000
#define SCAN_BLK 1024

// Scratch (allocation-free rule: __device__ globals)
__device__ float g_h1[(size_t)NMAX * HID];    // x @ W1
__device__ float g_agg1[(size_t)NMAX * HID];  // relu(scatter1 + b1)
__device__ float g_h2[(size_t)NMAX * C_OUT];  // agg1 @ W2

// CSR scratch
__device__ int   g_cnt[NMAX];
__device__ int   g_rowptr[NMAX + 1];
__device__ int   g_cursor[NMAX];
__device__ int   g_partial[(NMAX + SCAN_BLK - 1) / SCAN_BLK];
__device__ int   g_offs[(NMAX + SCAN_BLK - 1) / SCAN_BLK];
__device__ int   g_csr_src[EMAX];
__device__ float g_csr_w[EMAX];

// ---------------------------------------------------------------------------
// helpers
// ---------------------------------------------------------------------------
__device__ __forceinline__ uint32_t f2tf32(float x) {
  uint32_t r;
  asm("cvt.rna.tf32.f32 %0, %1;" : "=r"(r) : "f"(x));
  return r;
}

__device__ __forceinline__ void mma_tf32(
    float* d, const uint32_t* a, const uint32_t* b, const float* c) {
  asm volatile(
      "mma.sync.aligned.m16n8k8.row.col.f32.tf32.tf32.f32 "
      "{%0,%1,%2,%3}, {%4,%5,%6,%7}, {%8,%9}, {%10,%11,%12,%13};"
      : "=f"(d[0]), "=f"(d[1]), "=f"(d[2]), "=f"(d[3])
      : "r"(a[0]), "r"(a[1]), "r"(a[2]), "r"(a[3]),
        "r"(b[0]), "r"(b[1]),
        "f"(c[0]), "f"(c[1]), "f"(c[2]), "f"(c[3]));
}

// ---------------------------------------------------------------------------
// GEMM1: H1[M,128] = X[M,256] @ W1[256,128], tf32 tensor cores.
// ---------------------------------------------------------------------------
#define G1_BK 32
#define G1_PAD 4
__global__ __launch_bounds__(256) void gemm1_kernel(
    const float* __restrict__ X, const float* __restrict__ W, int M) {
  __shared__ uint32_t As[G1_BK][128 + G1_PAD];
  __shared__ uint32_t Bs[G1_BK][HID + G1_PAD];

  const int t = threadIdx.x;
  const int row0 = blockIdx.x * 128;
  const int warp = t >> 5;
  const int lane = t & 31;
  const int g  = lane >> 2;
  const int tg = lane & 3;
  const int m_base = (warp & 3) * 32;
  const int n_base = (warp >> 2) * 64;

  float acc[2][8][4];
#pragma unroll
  for (int mt = 0; mt < 2; mt++)
#pragma unroll
    for (int nt = 0; nt < 8; nt++)
#pragma unroll
      for (int i = 0; i < 4; i++) acc[mt][nt][i] = 0.f;

  for (int k0 = 0; k0 < F_IN; k0 += G1_BK) {
#pragma unroll
    for (int i = 0; i < 4; i++) {
      int id = t + i * 256;
      int r = id >> 3;
      int c4 = id & 7;
      float4 v = make_float4(0.f, 0.f, 0.f, 0.f);
      int grow = row0 + r;
      if (grow < M) v = *(const float4*)(X + (size_t)grow * F_IN + k0 + c4 * 4);
      As[c4 * 4 + 0][r] = f2tf32(v.x);
      As[c4 * 4 + 1][r] = f2tf32(v.y);
      As[c4 * 4 + 2][r] = f2tf32(v.z);
      As[c4 * 4 + 3][r] = f2tf32(v.w);
    }
#pragma unroll
    for (int i = 0; i < 4; i++) {
      int id = t + i * 256;
      int r = id >> 5;
      int c4 = id & 31;
      float4 v = *(const float4*)(W + (size_t)(k0 + r) * HID + c4 * 4);
      Bs[r][c4 * 4 + 0] = f2tf32(v.x);
      Bs[r][c4 * 4 + 1] = f2tf32(v.y);
      Bs[r][c4 * 4 + 2] = f2tf32(v.z);
      Bs[r][c4 * 4 + 3] = f2tf32(v.w);
    }
    __syncthreads();

#pragma unroll
    for (int kk = 0; kk < G1_BK / 8; kk++) {
      uint32_t a[2][4];
#pragma unroll
      for (int mt = 0; mt < 2; mt++) {
        int mr = m_base + mt * 16;
        a[mt][0] = As[kk * 8 + tg    ][mr + g    ];
        a[mt][1] = As[kk * 8 + tg    ][mr + g + 8];
        a[mt][2] = As[kk * 8 + tg + 4][mr + g    ];
        a[mt][3] = As[kk * 8 + tg + 4][mr + g + 8];
      }
#pragma unroll
      for (int nt = 0; nt < 8; nt++) {
        uint32_t b[2];
        b[0] = Bs[kk * 8 + tg    ][n_base + nt * 8 + g];
        b[1] = Bs[kk * 8 + tg + 4][n_base + nt * 8 + g];
        mma_tf32(acc[0][nt], a[0], b, acc[0][nt]);
        mma_tf32(acc[1][nt], a[1], b, acc[1][nt]);
      }
    }
    __syncthreads();
  }

#pragma unroll
  for (int mt = 0; mt < 2; mt++) {
    int r1 = row0 + m_base + mt * 16 + g;
    int r2 = r1 + 8;
#pragma unroll
    for (int nt = 0; nt < 8; nt++) {
      int col = n_base + nt * 8 + tg * 2;
      if (r1 < M) *(float2*)(g_h1 + (size_t)r1 * HID + col) =
          make_float2(acc[mt][nt][0], acc[mt][nt][1]);
      if (r2 < M) *(float2*)(g_h1 + (size_t)r2 * HID + col) =
          make_float2(acc[mt][nt][2], acc[mt][nt][3]);
    }
  }
}

// ---------------------------------------------------------------------------
// CSR build
// ---------------------------------------------------------------------------
__global__ void zero_cnt_kernel(int M) {
  int i = blockIdx.x * blockDim.x + threadIdx.x;
  if (i < M) g_cnt[i] = 0;
}

__global__ void hist_kernel(const int* __restrict__ ei, int E) {
  int e = blockIdx.x * blockDim.x + threadIdx.x;
  if (e < E) atomicAdd(&g_cnt[__ldg(ei + E + e)], 1);
}

// scan phase A: per-block sums of g_cnt
__global__ __launch_bounds__(SCAN_BLK) void scanA_kernel(int M) {
  __shared__ int s[SCAN_BLK];
  int t = threadIdx.x;
  int i = blockIdx.x * SCAN_BLK + t;
  int v = (i < M) ? g_cnt[i] : 0;
  s[t] = v;
  __syncthreads();
#pragma unroll
  for (int d = SCAN_BLK / 2; d > 0; d >>= 1) {
    if (t < d) s[t] += s[t + d];
    __syncthreads();
  }
  if (t == 0) g_partial[blockIdx.x] = s[0];
}

// scan phase B: exclusive scan of block partials (single block)
__global__ __launch_bounds__(SCAN_BLK) void scanB_kernel(int nblk, int M, int E) {
  __shared__ int s[2][SCAN_BLK];
  int t = threadIdx.x;
  int v = (t < nblk) ? g_partial[t] : 0;
  s[0][t] = v;
  __syncthreads();
  int cur = 0;
#pragma unroll
  for (int d = 1; d < SCAN_BLK; d <<= 1) {
    int nxt = cur ^ 1;
    int val = s[cur][t];
    if (t >= d) val += s[cur][t - d];
    s[nxt][t] = val;
    __syncthreads();
    cur = nxt;
  }
  if (t < nblk) g_offs[t] = s[cur][t] - v;  // exclusive
  if (t == 0) g_rowptr[M] = E;
}

// scan phase C: per-block inclusive scan + offset -> exclusive rowptr & cursor
__global__ __launch_bounds__(SCAN_BLK) void scanC_kernel(int M) {
  __shared__ int s[2][SCAN_BLK];
  int t = threadIdx.x;
  int i = blockIdx.x * SCAN_BLK + t;
  int v = (i < M) ? g_cnt[i] : 0;
  s[0][t] = v;
  __syncthreads();
  int cur = 0;
#pragma unroll
  for (int d = 1; d < SCAN_BLK; d <<= 1) {
    int nxt = cur ^ 1;
    int val = s[cur][t];
    if (t >= d) val += s[cur][t - d];
    s[nxt][t] = val;
    __syncthreads();
    cur = nxt;
  }
  if (i < M) {
    int excl = s[cur][t] - v + g_offs[blockIdx.x];
    g_rowptr[i] = excl;
    g_cursor[i] = excl;
  }
}

__global__ void fill_kernel(const int* __restrict__ ei,
                            const float* __restrict__ ew, int E) {
  int e = blockIdx.x * blockDim.x + threadIdx.x;
  if (e >= E) return;
  int src = __ldg(ei + e);
  int dst = __ldg(ei + E + e);
  int pos = atomicAdd(&g_cursor[dst], 1);
  g_csr_src[pos] = src;
  g_csr_w[pos] = __ldg(ew + e);
}

// ---------------------------------------------------------------------------
// agg1: one warp per dst row; acc = b1; acc += w*h1[src]; write relu(acc).
// ---------------------------------------------------------------------------
__global__ __launch_bounds__(256) void agg1_kernel(
    const float* __restrict__ b1, int M) {
  int row = blockIdx.x * 8 + (threadIdx.x >> 5);
  if (row >= M) return;
  int lane = threadIdx.x & 31;
  int beg = __ldg(&g_rowptr[row]);
  int end = __ldg(&g_rowptr[row + 1]);

  float4 acc = *(const float4*)(b1 + lane * 4);

  int e = beg;
  for (; e + 4 <= end; e += 4) {
    int   s0 = g_csr_src[e],     s1 = g_csr_src[e + 1];
    int   s2 = g_csr_src[e + 2], s3 = g_csr_src[e + 3];
    float w0 = g_csr_w[e],       w1 = g_csr_w[e + 1];
    float w2 = g_csr_w[e + 2],   w3 = g_csr_w[e + 3];
    float4 v0 = *(const float4*)(g_h1 + (size_t)s0 * HID + lane * 4);
    float4 v1 = *(const float4*)(g_h1 + (size_t)s1 * HID + lane * 4);
    float4 v2 = *(const float4*)(g_h1 + (size_t)s2 * HID + lane * 4);
    float4 v3 = *(const float4*)(g_h1 + (size_t)s3 * HID + lane * 4);
    acc.x += w0 * v0.x + w1 * v1.x + w2 * v2.x + w3 * v3.x;
    acc.y += w0 * v0.y + w1 * v1.y + w2 * v2.y + w3 * v3.y;
    acc.z += w0 * v0.z + w1 * v1.z + w2 * v2.z + w3 * v3.z;
    acc.w += w0 * v0.w + w1 * v1.w + w2 * v2.w + w3 * v3.w;
  }
  for (; e < end; e++) {
    int   s0 = g_csr_src[e];
    float w0 = g_csr_w[e];
    float4 v0 = *(const float4*)(g_h1 + (size_t)s0 * HID + lane * 4);
    acc.x += w0 * v0.x; acc.y += w0 * v0.y;
    acc.z += w0 * v0.z; acc.w += w0 * v0.w;
  }
  // fused ReLU
  acc.x = fmaxf(acc.x, 0.f); acc.y = fmaxf(acc.y, 0.f);
  acc.z = fmaxf(acc.z, 0.f); acc.w = fmaxf(acc.w, 0.f);
  *(float4*)(g_agg1 + (size_t)row * HID + lane * 4) = acc;
}

// ---------------------------------------------------------------------------
// GEMM2: H2[M,40] = agg1[M,128] @ W2[128,40]  (agg1 already relu'd)
// ---------------------------------------------------------------------------
__global__ __launch_bounds__(128) void gemm2_kernel(
    const float* __restrict__ W, int M) {
  __shared__ float Hs[32][HID];
  __shared__ float Ws[HID][C_OUT];
  const int t = threadIdx.x;
  const int row0 = blockIdx.x * 32;

  for (int i = t; i < HID * C_OUT; i += 128) Ws[i / C_OUT][i % C_OUT] = __ldg(W + i);
  for (int i = t; i < 32 * 32; i += 128) {
    int r = i >> 5, c4 = i & 31;
    int grow = row0 + r;
    float4 v = make_float4(0.f, 0.f, 0.f, 0.f);
    if (grow < M) v = *(const float4*)(g_agg1 + (size_t)grow * HID + c4 * 4);
    *(float4*)(&Hs[r][c4 * 4]) = v;
  }
  __syncthreads();

  const int warp = t >> 5, lane = t & 31;
  const int rbase = warp * 8;
  const bool has2 = lane < 8;
  float acc[8][2];
#pragma unroll
  for (int r = 0; r < 8; r++) { acc[r][0] = 0.f; acc[r][1] = 0.f; }

  for (int k = 0; k < HID; k += 4) {
    float hk[8][4];
#pragma unroll
    for (int r = 0; r < 8; r++) {
      float4 h4 = *(const float4*)(&Hs[rbase + r][k]);
      hk[r][0] = h4.x; hk[r][1] = h4.y; hk[r][2] = h4.z; hk[r][3] = h4.w;
    }
#pragma unroll
    for (int kk = 0; kk < 4; kk++) {
      float w0 = Ws[k + kk][lane];
      float w1 = has2 ? Ws[k + kk][lane + 32] : 0.f;
#pragma unroll
      for (int r = 0; r < 8; r++) {
        acc[r][0] += hk[r][kk] * w0;
        acc[r][1] += hk[r][kk] * w1;
      }
    }
  }
#pragma unroll
  for (int r = 0; r < 8; r++) {
    int grow = row0 + rbase + r;
    if (grow < M) {
      g_h2[(size_t)grow * C_OUT + lane] = acc[r][0];
      if (has2) g_h2[(size_t)grow * C_OUT + lane + 32] = acc[r][1];
    }
  }
}

// ---------------------------------------------------------------------------
// agg2 + bias + log_softmax, fused. One warp per dst row (40 cols:
// lane handles col=lane; lanes 0..7 also col=lane+32).
// ---------------------------------------------------------------------------
__global__ __launch_bounds__(256) void agg2_kernel(
    const float* __restrict__ b2, float* __restrict__ out, int M) {
  int row = blockIdx.x * 8 + (threadIdx.x >> 5);
  if (row >= M) return;
  int lane = threadIdx.x & 31;
  const bool has2 = lane < 8;
  int beg = __ldg(&g_rowptr[row]);
  int end = __ldg(&g_rowptr[row + 1]);

  float a0 = __ldg(b2 + lane);
  float a1 = has2 ? __ldg(b2 + lane + 32) : 0.f;

  int e = beg;
  for (; e + 2 <= end; e += 2) {
    int   s0 = g_csr_src[e],   s1 = g_csr_src[e + 1];
    float w0 = g_csr_w[e],     w1 = g_csr_w[e + 1];
    const float* p0 = g_h2 + (size_t)s0 * C_OUT;
    const float* p1 = g_h2 + (size_t)s1 * C_OUT;
    float u0 = p0[lane], u1 = p1[lane];
    float q0 = has2 ? p0[lane + 32] : 0.f;
    float q1 = has2 ? p1[lane + 32] : 0.f;
    a0 += w0 * u0 + w1 * u1;
    a1 += w0 * q0 + w1 * q1;
  }
  if (e < end) {
    int   s0 = g_csr_src[e];
    float w0 = g_csr_w[e];
    const float* p0 = g_h2 + (size_t)s0 * C_OUT;
    a0 += w0 * p0[lane];
    if (has2) a1 += w0 * p0[lane + 32];
  }

  // log_softmax over the 40 values held by this warp
  float m = has2 ? fmaxf(a0, a1) : a0;
#pragma unroll
  for (int o = 16; o; o >>= 1) m = fmaxf(m, __shfl_xor_sync(0xffffffffu, m, o));
  float s = expf(a0 - m) + (has2 ? expf(a1 - m) : 0.f);
#pragma unroll
  for (int o = 16; o; o >>= 1) s += __shfl_xor_sync(0xffffffffu, s, o);
  float lse = m + logf(s);

  float* p = out + (size_t)row * C_OUT;
  p[lane] = a0 - lse;
  if (has2) p[lane + 32] = a1 - lse;
}

// ---------------------------------------------------------------------------
extern "C" void kernel_launch(void* const* d_in, const int* in_sizes, int n_in,
                              void* d_out, int out_size) {
  const float* x  = (const float*)d_in[0];
  const int*   ei = (const int*)d_in[1];   // int32
  const float* ew = (const float*)d_in[2];
  const float* W1 = (const float*)d_in[3];
  const float* b1 = (const float*)d_in[4];
  const float* W2 = (const float*)d_in[5];
  const float* b2 = (const float*)d_in[6];
  float* out      = (float*)d_out;

  const int M = in_sizes[0] / F_IN;
  const int E = in_sizes[2];
  const int nblk = (M + SCAN_BLK - 1) / SCAN_BLK;

  // GEMM1 first (longest) — overlaps nothing but fills pipeline
  gemm1_kernel<<<(M + 127) / 128, 256>>>(x, W1, M);

  // CSR build
  zero_cnt_kernel<<<(M + 255) / 256, 256>>>(M);
  hist_kernel<<<(E + 255) / 256, 256>>>(ei, E);
  scanA_kernel<<<nblk, SCAN_BLK>>>(M);
  scanB_kernel<<<1, SCAN_BLK>>>(nblk, M, E);
  scanC_kernel<<<nblk, SCAN_BLK>>>(M);
  fill_kernel<<<(E + 255) / 256, 256>>>(ei, ew, E);

  // Layer 1 aggregation (gather, no atomics) + bias + ReLU
  agg1_kernel<<<(M + 7) / 8, 256>>>(b1, M);

  // GEMM2
  gemm2_kernel<<<(M + 31) / 32, 128>>>(W2, M);

  // Layer 2 aggregation + bias + log_softmax (fused)
  agg2_kernel<<<(M + 7) / 8, 256>>>(b2, out, M);
}

// round 5
// speedup vs baseline: 2.2155x; 1.1418x over previous
#include <cuda_runtime.h>
#include <cuda_fp16.h>
#include <stdint.h>
#include <math.h>

#define F_IN  256
#define HID   128
#define C_OUT 40
#define NMAX  100000
#define EMAX  3200000
#define SCAN_BLK 1024

// Scratch (allocation-free rule: __device__ globals)
__device__ __half g_h1[(size_t)NMAX * HID];    // x @ W1, fp16 storage
__device__ float  g_agg1[(size_t)NMAX * HID];  // relu(agg + b1), fp32
__device__ __half g_h2[(size_t)NMAX * C_OUT];  // agg1 @ W2, fp16 storage

// CSR scratch
__device__ int   g_cnt[NMAX];
__device__ int   g_rowptr[NMAX + 1];
__device__ int   g_cursor[NMAX];
__device__ int   g_partial[(NMAX + SCAN_BLK - 1) / SCAN_BLK];
__device__ int   g_offs[(NMAX + SCAN_BLK - 1) / SCAN_BLK];
__device__ int   g_csr_src[EMAX];
__device__ float g_csr_w[EMAX];

// ---------------------------------------------------------------------------
// helpers
// ---------------------------------------------------------------------------
__device__ __forceinline__ uint32_t f2tf32(float x) {
  uint32_t r;
  asm("cvt.rna.tf32.f32 %0, %1;" : "=r"(r) : "f"(x));
  return r;
}

__device__ __forceinline__ void mma_tf32(
    float* d, const uint32_t* a, const uint32_t* b, const float* c) {
  asm volatile(
      "mma.sync.aligned.m16n8k8.row.col.f32.tf32.tf32.f32 "
      "{%0,%1,%2,%3}, {%4,%5,%6,%7}, {%8,%9}, {%10,%11,%12,%13};"
      : "=f"(d[0]), "=f"(d[1]), "=f"(d[2]), "=f"(d[3])
      : "r"(a[0]), "r"(a[1]), "r"(a[2]), "r"(a[3]),
        "r"(b[0]), "r"(b[1]),
        "f"(c[0]), "f"(c[1]), "f"(c[2]), "f"(c[3]));
}

// ---------------------------------------------------------------------------
// GEMM1: H1[M,128] = X[M,256] @ W1[256,128], tf32 MMA, fp16 output.
// ---------------------------------------------------------------------------
#define G1_BK 32
#define G1_PAD 4
__global__ __launch_bounds__(256) void gemm1_kernel(
    const float* __restrict__ X, const float* __restrict__ W, int M) {
  __shared__ uint32_t As[G1_BK][128 + G1_PAD];
  __shared__ uint32_t Bs[G1_BK][HID + G1_PAD];

  const int t = threadIdx.x;
  const int row0 = blockIdx.x * 128;
  const int warp = t >> 5;
  const int lane = t & 31;
  const int g  = lane >> 2;
  const int tg = lane & 3;
  const int m_base = (warp & 3) * 32;
  const int n_base = (warp >> 2) * 64;

  float acc[2][8][4];
#pragma unroll
  for (int mt = 0; mt < 2; mt++)
#pragma unroll
    for (int nt = 0; nt < 8; nt++)
#pragma unroll
      for (int i = 0; i < 4; i++) acc[mt][nt][i] = 0.f;

  for (int k0 = 0; k0 < F_IN; k0 += G1_BK) {
#pragma unroll
    for (int i = 0; i < 4; i++) {
      int id = t + i * 256;
      int r = id >> 3;
      int c4 = id & 7;
      float4 v = make_float4(0.f, 0.f, 0.f, 0.f);
      int grow = row0 + r;
      if (grow < M) v = *(const float4*)(X + (size_t)grow * F_IN + k0 + c4 * 4);
      As[c4 * 4 + 0][r] = f2tf32(v.x);
      As[c4 * 4 + 1][r] = f2tf32(v.y);
      As[c4 * 4 + 2][r] = f2tf32(v.z);
      As[c4 * 4 + 3][r] = f2tf32(v.w);
    }
#pragma unroll
    for (int i = 0; i < 4; i++) {
      int id = t + i * 256;
      int r = id >> 5;
      int c4 = id & 31;
      float4 v = *(const float4*)(W + (size_t)(k0 + r) * HID + c4 * 4);
      Bs[r][c4 * 4 + 0] = f2tf32(v.x);
      Bs[r][c4 * 4 + 1] = f2tf32(v.y);
      Bs[r][c4 * 4 + 2] = f2tf32(v.z);
      Bs[r][c4 * 4 + 3] = f2tf32(v.w);
    }
    __syncthreads();

#pragma unroll
    for (int kk = 0; kk < G1_BK / 8; kk++) {
      uint32_t a[2][4];
#pragma unroll
      for (int mt = 0; mt < 2; mt++) {
        int mr = m_base + mt * 16;
        a[mt][0] = As[kk * 8 + tg    ][mr + g    ];
        a[mt][1] = As[kk * 8 + tg    ][mr + g + 8];
        a[mt][2] = As[kk * 8 + tg + 4][mr + g    ];
        a[mt][3] = As[kk * 8 + tg + 4][mr + g + 8];
      }
#pragma unroll
      for (int nt = 0; nt < 8; nt++) {
        uint32_t b[2];
        b[0] = Bs[kk * 8 + tg    ][n_base + nt * 8 + g];
        b[1] = Bs[kk * 8 + tg + 4][n_base + nt * 8 + g];
        mma_tf32(acc[0][nt], a[0], b, acc[0][nt]);
        mma_tf32(acc[1][nt], a[1], b, acc[1][nt]);
      }
    }
    __syncthreads();
  }

#pragma unroll
  for (int mt = 0; mt < 2; mt++) {
    int r1 = row0 + m_base + mt * 16 + g;
    int r2 = r1 + 8;
#pragma unroll
    for (int nt = 0; nt < 8; nt++) {
      int col = n_base + nt * 8 + tg * 2;
      if (r1 < M) *(__half2*)(g_h1 + (size_t)r1 * HID + col) =
          __floats2half2_rn(acc[mt][nt][0], acc[mt][nt][1]);
      if (r2 < M) *(__half2*)(g_h1 + (size_t)r2 * HID + col) =
          __floats2half2_rn(acc[mt][nt][2], acc[mt][nt][3]);
    }
  }
}

// ---------------------------------------------------------------------------
// CSR build
// ---------------------------------------------------------------------------
__global__ void zero_cnt_kernel(int M) {
  int i = blockIdx.x * blockDim.x + threadIdx.x;
  if (i < M) g_cnt[i] = 0;
}

__global__ void hist_kernel(const int* __restrict__ ei, int E) {
  int e = blockIdx.x * blockDim.x + threadIdx.x;
  if (e < E) atomicAdd(&g_cnt[__ldg(ei + E + e)], 1);
}

__global__ __launch_bounds__(SCAN_BLK) void scanA_kernel(int M) {
  __shared__ int s[SCAN_BLK];
  int t = threadIdx.x;
  int i = blockIdx.x * SCAN_BLK + t;
  int v = (i < M) ? g_cnt[i] : 0;
  s[t] = v;
  __syncthreads();
#pragma unroll
  for (int d = SCAN_BLK / 2; d > 0; d >>= 1) {
    if (t < d) s[t] += s[t + d];
    __syncthreads();
  }
  if (t == 0) g_partial[blockIdx.x] = s[0];
}

__global__ __launch_bounds__(SCAN_BLK) void scanB_kernel(int nblk, int M, int E) {
  __shared__ int s[2][SCAN_BLK];
  int t = threadIdx.x;
  int v = (t < nblk) ? g_partial[t] : 0;
  s[0][t] = v;
  __syncthreads();
  int cur = 0;
#pragma unroll
  for (int d = 1; d < SCAN_BLK; d <<= 1) {
    int nxt = cur ^ 1;
    int val = s[cur][t];
    if (t >= d) val += s[cur][t - d];
    s[nxt][t] = val;
    __syncthreads();
    cur = nxt;
  }
  if (t < nblk) g_offs[t] = s[cur][t] - v;  // exclusive
  if (t == 0) g_rowptr[M] = E;
}

__global__ __launch_bounds__(SCAN_BLK) void scanC_kernel(int M) {
  __shared__ int s[2][SCAN_BLK];
  int t = threadIdx.x;
  int i = blockIdx.x * SCAN_BLK + t;
  int v = (i < M) ? g_cnt[i] : 0;
  s[0][t] = v;
  __syncthreads();
  int cur = 0;
#pragma unroll
  for (int d = 1; d < SCAN_BLK; d <<= 1) {
    int nxt = cur ^ 1;
    int val = s[cur][t];
    if (t >= d) val += s[cur][t - d];
    s[nxt][t] = val;
    __syncthreads();
    cur = nxt;
  }
  if (i < M) {
    int excl = s[cur][t] - v + g_offs[blockIdx.x];
    g_rowptr[i] = excl;
    g_cursor[i] = excl;
  }
}

__global__ void fill_kernel(const int* __restrict__ ei,
                            const float* __restrict__ ew, int E) {
  int e = blockIdx.x * blockDim.x + threadIdx.x;
  if (e >= E) return;
  int src = __ldg(ei + e);
  int dst = __ldg(ei + E + e);
  int pos = atomicAdd(&g_cursor[dst], 1);
  g_csr_src[pos] = src;
  g_csr_w[pos] = __ldg(ew + e);
}

// ---------------------------------------------------------------------------
// agg1: one warp per dst row; fp16 gather (8B/lane/edge), fp32 accumulate.
// Fused: +b1, ReLU.
// ---------------------------------------------------------------------------
__device__ __forceinline__ void acc_h1(float4& acc, float w, uint2 u) {
  float2 lo = __half22float2(*(__half2*)&u.x);
  float2 hi = __half22float2(*(__half2*)&u.y);
  acc.x += w * lo.x; acc.y += w * lo.y;
  acc.z += w * hi.x; acc.w += w * hi.y;
}

__global__ __launch_bounds__(256) void agg1_kernel(
    const float* __restrict__ b1, int M) {
  int row = blockIdx.x * 8 + (threadIdx.x >> 5);
  if (row >= M) return;
  int lane = threadIdx.x & 31;
  int beg = g_rowptr[row];
  int end = g_rowptr[row + 1];

  float4 acc = *(const float4*)(b1 + lane * 4);

  int e = beg;
  for (; e + 4 <= end; e += 4) {
    int   s0 = g_csr_src[e],     s1 = g_csr_src[e + 1];
    int   s2 = g_csr_src[e + 2], s3 = g_csr_src[e + 3];
    float w0 = g_csr_w[e],       w1 = g_csr_w[e + 1];
    float w2 = g_csr_w[e + 2],   w3 = g_csr_w[e + 3];
    uint2 u0 = *(const uint2*)(g_h1 + (size_t)s0 * HID + lane * 4);
    uint2 u1 = *(const uint2*)(g_h1 + (size_t)s1 * HID + lane * 4);
    uint2 u2 = *(const uint2*)(g_h1 + (size_t)s2 * HID + lane * 4);
    uint2 u3 = *(const uint2*)(g_h1 + (size_t)s3 * HID + lane * 4);
    acc_h1(acc, w0, u0);
    acc_h1(acc, w1, u1);
    acc_h1(acc, w2, u2);
    acc_h1(acc, w3, u3);
  }
  for (; e < end; e++) {
    int   s0 = g_csr_src[e];
    float w0 = g_csr_w[e];
    uint2 u0 = *(const uint2*)(g_h1 + (size_t)s0 * HID + lane * 4);
    acc_h1(acc, w0, u0);
  }
  acc.x = fmaxf(acc.x, 0.f); acc.y = fmaxf(acc.y, 0.f);
  acc.z = fmaxf(acc.z, 0.f); acc.w = fmaxf(acc.w, 0.f);
  *(float4*)(g_agg1 + (size_t)row * HID + lane * 4) = acc;
}

// ---------------------------------------------------------------------------
// GEMM2: H2[M,40] = agg1[M,128] @ W2[128,40], tf32 MMA, fp16 output.
// Block: 128 threads = 4 warps, 64 rows (warp = m16); 5 n8-tiles; BK=32.
// ---------------------------------------------------------------------------
#define G2_BK 32
__global__ __launch_bounds__(128) void gemm2_kernel(
    const float* __restrict__ W, int M) {
  __shared__ uint32_t As[G2_BK][64 + 4];
  __shared__ uint32_t Bs[G2_BK][48];

  const int t = threadIdx.x;
  const int row0 = blockIdx.x * 64;
  const int warp = t >> 5;
  const int lane = t & 31;
  const int g  = lane >> 2;
  const int tg = lane & 3;
  const int m_base = warp * 16;

  float acc[5][4];
#pragma unroll
  for (int nt = 0; nt < 5; nt++)
#pragma unroll
    for (int i = 0; i < 4; i++) acc[nt][i] = 0.f;

  for (int k0 = 0; k0 < HID; k0 += G2_BK) {
    // A tile: 64 rows x 32 cols = 512 float4, 4 per thread
#pragma unroll
    for (int i = 0; i < 4; i++) {
      int id = t + i * 128;
      int r = id >> 3;     // 0..63
      int c4 = id & 7;     // 0..7
      int grow = row0 + r;
      float4 v = make_float4(0.f, 0.f, 0.f, 0.f);
      if (grow < M) v = *(const float4*)(g_agg1 + (size_t)grow * HID + k0 + c4 * 4);
      As[c4 * 4 + 0][r] = f2tf32(v.x);
      As[c4 * 4 + 1][r] = f2tf32(v.y);
      As[c4 * 4 + 2][r] = f2tf32(v.z);
      As[c4 * 4 + 3][r] = f2tf32(v.w);
    }
    // B tile: 32 rows x 40 cols = 1280, 10 per thread
#pragma unroll
    for (int i = 0; i < 10; i++) {
      int id = t + i * 128;
      int r = id / C_OUT, c = id % C_OUT;
      Bs[r][c] = f2tf32(__ldg(W + (size_t)(k0 + r) * C_OUT + c));
    }
    __syncthreads();

#pragma unroll
    for (int kk = 0; kk < G2_BK / 8; kk++) {
      uint32_t a[4];
      a[0] = As[kk * 8 + tg    ][m_base + g    ];
      a[1] = As[kk * 8 + tg    ][m_base + g + 8];
      a[2] = As[kk * 8 + tg + 4][m_base + g    ];
      a[3] = As[kk * 8 + tg + 4][m_base + g + 8];
#pragma unroll
      for (int nt = 0; nt < 5; nt++) {
        uint32_t b[2];
        b[0] = Bs[kk * 8 + tg    ][nt * 8 + g];
        b[1] = Bs[kk * 8 + tg + 4][nt * 8 + g];
        mma_tf32(acc[nt], a, b, acc[nt]);
      }
    }
    __syncthreads();
  }

  int r1 = row0 + m_base + g;
  int r2 = r1 + 8;
#pragma unroll
  for (int nt = 0; nt < 5; nt++) {
    int col = nt * 8 + tg * 2;
    if (r1 < M) *(__half2*)(g_h2 + (size_t)r1 * C_OUT + col) =
        __floats2half2_rn(acc[nt][0], acc[nt][1]);
    if (r2 < M) *(__half2*)(g_h2 + (size_t)r2 * C_OUT + col) =
        __floats2half2_rn(acc[nt][2], acc[nt][3]);
  }
}

// ---------------------------------------------------------------------------
// agg2 + bias + log_softmax, fused. One warp per dst row; fp16 gather.
// ---------------------------------------------------------------------------
__global__ __launch_bounds__(256) void agg2_kernel(
    const float* __restrict__ b2, float* __restrict__ out, int M) {
  int row = blockIdx.x * 8 + (threadIdx.x >> 5);
  if (row >= M) return;
  int lane = threadIdx.x & 31;
  const bool has2 = lane < 8;
  int beg = g_rowptr[row];
  int end = g_rowptr[row + 1];

  float a0 = __ldg(b2 + lane);
  float a1 = has2 ? __ldg(b2 + lane + 32) : 0.f;

  int e = beg;
  for (; e + 2 <= end; e += 2) {
    int   s0 = g_csr_src[e],   s1 = g_csr_src[e + 1];
    float w0 = g_csr_w[e],     w1 = g_csr_w[e + 1];
    const __half* p0 = g_h2 + (size_t)s0 * C_OUT;
    const __half* p1 = g_h2 + (size_t)s1 * C_OUT;
    float u0 = __half2float(p0[lane]);
    float u1 = __half2float(p1[lane]);
    a0 += w0 * u0 + w1 * u1;
    if (has2) {
      a1 += w0 * __half2float(p0[lane + 32]) + w1 * __half2float(p1[lane + 32]);
    }
  }
  if (e < end) {
    int   s0 = g_csr_src[e];
    float w0 = g_csr_w[e];
    const __half* p0 = g_h2 + (size_t)s0 * C_OUT;
    a0 += w0 * __half2float(p0[lane]);
    if (has2) a1 += w0 * __half2float(p0[lane + 32]);
  }

  float m = has2 ? fmaxf(a0, a1) : a0;
#pragma unroll
  for (int o = 16; o; o >>= 1) m = fmaxf(m, __shfl_xor_sync(0xffffffffu, m, o));
  float s = expf(a0 - m) + (has2 ? expf(a1 - m) : 0.f);
#pragma unroll
  for (int o = 16; o; o >>= 1) s += __shfl_xor_sync(0xffffffffu, s, o);
  float lse = m + logf(s);

  float* p = out + (size_t)row * C_OUT;
  p[lane] = a0 - lse;
  if (has2) p[lane + 32] = a1 - lse;
}

// ---------------------------------------------------------------------------
extern "C" void kernel_launch(void* const* d_in, const int* in_sizes, int n_in,
                              void* d_out, int out_size) {
  const float* x  = (const float*)d_in[0];
  const int*   ei = (const int*)d_in[1];   // int32
  const float* ew = (const float*)d_in[2];
  const float* W1 = (const float*)d_in[3];
  const float* b1 = (const float*)d_in[4];
  const float* W2 = (const float*)d_in[5];
  const float* b2 = (const float*)d_in[6];
  float* out      = (float*)d_out;

  const int M = in_sizes[0] / F_IN;
  const int E = in_sizes[2];
  const int nblk = (M + SCAN_BLK - 1) / SCAN_BLK;

  gemm1_kernel<<<(M + 127) / 128, 256>>>(x, W1, M);

  // CSR build
  zero_cnt_kernel<<<(M + 255) / 256, 256>>>(M);
  hist_kernel<<<(E + 255) / 256, 256>>>(ei, E);
  scanA_kernel<<<nblk, SCAN_BLK>>>(M);
  scanB_kernel<<<1, SCAN_BLK>>>(nblk, M, E);
  scanC_kernel<<<nblk, SCAN_BLK>>>(M);
  fill_kernel<<<(E + 255) / 256, 256>>>(ei, ew, E);

  // Layer 1 aggregation (fp16 gather) + bias + ReLU
  agg1_kernel<<<(M + 7) / 8, 256>>>(b1, M);

  // GEMM2 (tf32 MMA, fp16 output)
  gemm2_kernel<<<(M + 63) / 64, 128>>>(W2, M);

  // Layer 2 aggregation + bias + log_softmax
  agg2_kernel<<<(M + 7) / 8, 256>>>(b2, out, M);
}

// round 7
// speedup vs baseline: 2.5323x; 1.1429x over previous
#include <cuda_runtime.h>
#include <cuda_fp16.h>
#include <stdint.h>
#include <math.h>

#define F_IN  256
#define HID   128
#define C_OUT 40
#define NMAX  100000
#define EMAX  3200000
#define SCAN_BLK 1024

// Scratch (allocation-free rule: __device__ globals)
__device__ __half g_h1[(size_t)NMAX * HID];    // x @ W1, fp16 storage
__device__ float  g_agg1[(size_t)NMAX * HID];  // relu(agg + b1), fp32
__device__ __half g_h2[(size_t)NMAX * C_OUT];  // agg1 @ W2, fp16 storage

// CSR scratch
__device__ int   g_cnt[NMAX];
__device__ int   g_rowptr[NMAX + 1];
__device__ int   g_cursor[NMAX];
__device__ int   g_partial[(NMAX + SCAN_BLK - 1) / SCAN_BLK];
__device__ int   g_offs[(NMAX + SCAN_BLK - 1) / SCAN_BLK];
__device__ uint2 g_csr[EMAX];   // .x = src, .y = weight bits

// ---------------------------------------------------------------------------
// helpers
// ---------------------------------------------------------------------------
__device__ __forceinline__ uint32_t f2tf32(float x) {
  uint32_t r;
  asm("cvt.rna.tf32.f32 %0, %1;" : "=r"(r) : "f"(x));
  return r;
}

__device__ __forceinline__ void mma_tf32(
    float* d, const uint32_t* a, const uint32_t* b, const float* c) {
  asm volatile(
      "mma.sync.aligned.m16n8k8.row.col.f32.tf32.tf32.f32 "
      "{%0,%1,%2,%3}, {%4,%5,%6,%7}, {%8,%9}, {%10,%11,%12,%13};"
      : "=f"(d[0]), "=f"(d[1]), "=f"(d[2]), "=f"(d[3])
      : "r"(a[0]), "r"(a[1]), "r"(a[2]), "r"(a[3]),
        "r"(b[0]), "r"(b[1]),
        "f"(c[0]), "f"(c[1]), "f"(c[2]), "f"(c[3]));
}

#define CP_ASYNC16(dst_u32, src_ptr) \
  asm volatile("cp.async.ca.shared.global [%0], [%1], 16;" \
               :: "r"(dst_u32), "l"(src_ptr))
#define CP_COMMIT() asm volatile("cp.async.commit_group;")
#define CP_WAIT1()  asm volatile("cp.async.wait_group 1;")

// ---------------------------------------------------------------------------
// GEMM1: H1[M,128] = X[M,256] @ W1[256,128]
// 2-stage cp.async pipeline (raw fp32 in smem), cvt.rna.tf32 in registers
// right before MMA (RNA rounding preserved). BK=16, block 256 thr (4m x 2n
// warps), warp tile 32x64.
// ---------------------------------------------------------------------------
#define G1_BK 16
#define AS_LD 20
#define BS_LD 132
__global__ __launch_bounds__(256) void gemm1_kernel(
    const float* __restrict__ X, const float* __restrict__ W, int M) {
  __shared__ float As[2][128][AS_LD];   // [m][k]
  __shared__ float Bs[2][G1_BK][BS_LD]; // [k][n]

  const int t = threadIdx.x;
  const int row0 = blockIdx.x * 128;
  const int warp = t >> 5;
  const int lane = t & 31;
  const int g  = lane >> 2;
  const int tg = lane & 3;
  const int m_base = (warp & 3) * 32;
  const int n_base = (warp >> 2) * 64;

  const int ar0 = (t * 2) >> 2;
  const int ac0 = (t * 2) & 3;
  const int ar1 = (t * 2 + 1) >> 2;
  const int ac1 = (t * 2 + 1) & 3;
  const int br0 = (t * 2) >> 5;
  const int bc0 = (t * 2) & 31;
  const int br1 = (t * 2 + 1) >> 5;
  const int bc1 = (t * 2 + 1) & 31;

  const int garow0 = row0 + ar0 < M ? row0 + ar0 : M - 1;
  const int garow1 = row0 + ar1 < M ? row0 + ar1 : M - 1;

  auto prefetch = [&](int k0, int s) {
    uint32_t a_dst0 = (uint32_t)__cvta_generic_to_shared(&As[s][ar0][ac0 * 4]);
    uint32_t a_dst1 = (uint32_t)__cvta_generic_to_shared(&As[s][ar1][ac1 * 4]);
    CP_ASYNC16(a_dst0, X + (size_t)garow0 * F_IN + k0 + ac0 * 4);
    CP_ASYNC16(a_dst1, X + (size_t)garow1 * F_IN + k0 + ac1 * 4);
    uint32_t b_dst0 = (uint32_t)__cvta_generic_to_shared(&Bs[s][br0][bc0 * 4]);
    uint32_t b_dst1 = (uint32_t)__cvta_generic_to_shared(&Bs[s][br1][bc1 * 4]);
    CP_ASYNC16(b_dst0, W + (size_t)(k0 + br0) * HID + bc0 * 4);
    CP_ASYNC16(b_dst1, W + (size_t)(k0 + br1) * HID + bc1 * 4);
    CP_COMMIT();
  };

  float acc[2][8][4];
#pragma unroll
  for (int mt = 0; mt < 2; mt++)
#pragma unroll
    for (int nt = 0; nt < 8; nt++)
#pragma unroll
      for (int i = 0; i < 4; i++) acc[mt][nt][i] = 0.f;

  prefetch(0, 0);
  prefetch(G1_BK, 1);

  const int NCHUNK = F_IN / G1_BK;  // 16
#pragma unroll 1
  for (int c = 0; c < NCHUNK; c++) {
    int s = c & 1;
    CP_WAIT1();
    __syncthreads();

#pragma unroll
    for (int kk = 0; kk < G1_BK / 8; kk++) {
      uint32_t a[2][4];
#pragma unroll
      for (int mt = 0; mt < 2; mt++) {
        int mr = m_base + mt * 16;
        a[mt][0] = f2tf32(As[s][mr + g    ][kk * 8 + tg    ]);
        a[mt][1] = f2tf32(As[s][mr + g + 8][kk * 8 + tg    ]);
        a[mt][2] = f2tf32(As[s][mr + g    ][kk * 8 + tg + 4]);
        a[mt][3] = f2tf32(As[s][mr + g + 8][kk * 8 + tg + 4]);
      }
#pragma unroll
      for (int nt = 0; nt < 8; nt++) {
        uint32_t b[2];
        b[0] = f2tf32(Bs[s][kk * 8 + tg    ][n_base + nt * 8 + g]);
        b[1] = f2tf32(Bs[s][kk * 8 + tg + 4][n_base + nt * 8 + g]);
        mma_tf32(acc[0][nt], a[0], b, acc[0][nt]);
        mma_tf32(acc[1][nt], a[1], b, acc[1][nt]);
      }
    }
    __syncthreads();
    if (c + 2 < NCHUNK) prefetch((c + 2) * G1_BK, s);
  }

#pragma unroll
  for (int mt = 0; mt < 2; mt++) {
    int r1 = row0 + m_base + mt * 16 + g;
    int r2 = r1 + 8;
#pragma unroll
    for (int nt = 0; nt < 8; nt++) {
      int col = n_base + nt * 8 + tg * 2;
      if (r1 < M) *(__half2*)(g_h1 + (size_t)r1 * HID + col) =
          __floats2half2_rn(acc[mt][nt][0], acc[mt][nt][1]);
      if (r2 < M) *(__half2*)(g_h1 + (size_t)r2 * HID + col) =
          __floats2half2_rn(acc[mt][nt][2], acc[mt][nt][3]);
    }
  }
}

// ---------------------------------------------------------------------------
// CSR build
// ---------------------------------------------------------------------------
__global__ void zero_cnt_kernel(int M) {
  int i = blockIdx.x * blockDim.x + threadIdx.x;
  if (i < M) g_cnt[i] = 0;
}

__global__ void hist_kernel(const int* __restrict__ ei, int E) {
  int e = blockIdx.x * blockDim.x + threadIdx.x;
  if (e < E) atomicAdd(&g_cnt[__ldg(ei + E + e)], 1);
}

__global__ __launch_bounds__(SCAN_BLK) void scanA_kernel(int M) {
  __shared__ int s[SCAN_BLK];
  int t = threadIdx.x;
  int i = blockIdx.x * SCAN_BLK + t;
  int v = (i < M) ? g_cnt[i] : 0;
  s[t] = v;
  __syncthreads();
#pragma unroll
  for (int d = SCAN_BLK / 2; d > 0; d >>= 1) {
    if (t < d) s[t] += s[t + d];
    __syncthreads();
  }
  if (t == 0) g_partial[blockIdx.x] = s[0];
}

__global__ __launch_bounds__(SCAN_BLK) void scanB_kernel(int nblk, int M, int E) {
  __shared__ int s[2][SCAN_BLK];
  int t = threadIdx.x;
  int v = (t < nblk) ? g_partial[t] : 0;
  s[0][t] = v;
  __syncthreads();
  int cur = 0;
#pragma unroll
  for (int d = 1; d < SCAN_BLK; d <<= 1) {
    int nxt = cur ^ 1;
    int val = s[cur][t];
    if (t >= d) val += s[cur][t - d];
    s[nxt][t] = val;
    __syncthreads();
    cur = nxt;
  }
  if (t < nblk) g_offs[t] = s[cur][t] - v;
  if (t == 0) g_rowptr[M] = E;
}

__global__ __launch_bounds__(SCAN_BLK) void scanC_kernel(int M) {
  __shared__ int s[2][SCAN_BLK];
  int t = threadIdx.x;
  int i = blockIdx.x * SCAN_BLK + t;
  int v = (i < M) ? g_cnt[i] : 0;
  s[0][t] = v;
  __syncthreads();
  int cur = 0;
#pragma unroll
  for (int d = 1; d < SCAN_BLK; d <<= 1) {
    int nxt = cur ^ 1;
    int val = s[cur][t];
    if (t >= d) val += s[cur][t - d];
    s[nxt][t] = val;
    __syncthreads();
    cur = nxt;
  }
  if (i < M) {
    int excl = s[cur][t] - v + g_offs[blockIdx.x];
    g_rowptr[i] = excl;
    g_cursor[i] = excl;
  }
}

__global__ void fill_kernel(const int* __restrict__ ei,
                            const float* __restrict__ ew, int E) {
  int e = blockIdx.x * blockDim.x + threadIdx.x;
  if (e >= E) return;
  int src = __ldg(ei + e);
  int dst = __ldg(ei + E + e);
  int pos = atomicAdd(&g_cursor[dst], 1);
  g_csr[pos] = make_uint2((unsigned)src, __float_as_uint(__ldg(ew + e)));
}

// ---------------------------------------------------------------------------
// agg1: one warp per dst row; fp16 gather, fp32 accumulate; unroll 8 (MLP).
// Fused: +b1, ReLU.
// ---------------------------------------------------------------------------
__device__ __forceinline__ void acc_h1(float4& acc, float w, uint2 u) {
  float2 lo = __half22float2(*(__half2*)&u.x);
  float2 hi = __half22float2(*(__half2*)&u.y);
  acc.x += w * lo.x; acc.y += w * lo.y;
  acc.z += w * hi.x; acc.w += w * hi.y;
}

__global__ __launch_bounds__(256) void agg1_kernel(
    const float* __restrict__ b1, int M) {
  int row = blockIdx.x * 8 + (threadIdx.x >> 5);
  if (row >= M) return;
  int lane = threadIdx.x & 31;
  int beg = g_rowptr[row];
  int end = g_rowptr[row + 1];

  float4 acc = *(const float4*)(b1 + lane * 4);

  int e = beg;
  for (; e + 8 <= end; e += 8) {
    uint2 c0 = g_csr[e],     c1 = g_csr[e + 1];
    uint2 c2 = g_csr[e + 2], c3 = g_csr[e + 3];
    uint2 c4 = g_csr[e + 4], c5 = g_csr[e + 5];
    uint2 c6 = g_csr[e + 6], c7 = g_csr[e + 7];
    uint2 u0 = *(const uint2*)(g_h1 + (size_t)c0.x * HID + lane * 4);
    uint2 u1 = *(const uint2*)(g_h1 + (size_t)c1.x * HID + lane * 4);
    uint2 u2 = *(const uint2*)(g_h1 + (size_t)c2.x * HID + lane * 4);
    uint2 u3 = *(const uint2*)(g_h1 + (size_t)c3.x * HID + lane * 4);
    uint2 u4 = *(const uint2*)(g_h1 + (size_t)c4.x * HID + lane * 4);
    uint2 u5 = *(const uint2*)(g_h1 + (size_t)c5.x * HID + lane * 4);
    uint2 u6 = *(const uint2*)(g_h1 + (size_t)c6.x * HID + lane * 4);
    uint2 u7 = *(const uint2*)(g_h1 + (size_t)c7.x * HID + lane * 4);
    acc_h1(acc, __uint_as_float(c0.y), u0);
    acc_h1(acc, __uint_as_float(c1.y), u1);
    acc_h1(acc, __uint_as_float(c2.y), u2);
    acc_h1(acc, __uint_as_float(c3.y), u3);
    acc_h1(acc, __uint_as_float(c4.y), u4);
    acc_h1(acc, __uint_as_float(c5.y), u5);
    acc_h1(acc, __uint_as_float(c6.y), u6);
    acc_h1(acc, __uint_as_float(c7.y), u7);
  }
  for (; e < end; e++) {
    uint2 c0 = g_csr[e];
    uint2 u0 = *(const uint2*)(g_h1 + (size_t)c0.x * HID + lane * 4);
    acc_h1(acc, __uint_as_float(c0.y), u0);
  }
  acc.x = fmaxf(acc.x, 0.f); acc.y = fmaxf(acc.y, 0.f);
  acc.z = fmaxf(acc.z, 0.f); acc.w = fmaxf(acc.w, 0.f);
  *(float4*)(g_agg1 + (size_t)row * HID + lane * 4) = acc;
}

// ---------------------------------------------------------------------------
// GEMM2: H2[M,40] = agg1[M,128] @ W2[128,40], tf32 MMA (RNA cvt), fp16 out.
// ---------------------------------------------------------------------------
#define G2_BK 32
__global__ __launch_bounds__(128) void gemm2_kernel(
    const float* __restrict__ W, int M) {
  __shared__ float As[G2_BK][64 + 4];
  __shared__ float Bs[G2_BK][48];

  const int t = threadIdx.x;
  const int row0 = blockIdx.x * 64;
  const int warp = t >> 5;
  const int lane = t & 31;
  const int g  = lane >> 2;
  const int tg = lane & 3;
  const int m_base = warp * 16;

  float acc[5][4];
#pragma unroll
  for (int nt = 0; nt < 5; nt++)
#pragma unroll
    for (int i = 0; i < 4; i++) acc[nt][i] = 0.f;

  for (int k0 = 0; k0 < HID; k0 += G2_BK) {
#pragma unroll
    for (int i = 0; i < 4; i++) {
      int id = t + i * 128;
      int r = id >> 3;
      int c4 = id & 7;
      int grow = row0 + r;
      float4 v = make_float4(0.f, 0.f, 0.f, 0.f);
      if (grow < M) v = *(const float4*)(g_agg1 + (size_t)grow * HID + k0 + c4 * 4);
      As[c4 * 4 + 0][r] = v.x;
      As[c4 * 4 + 1][r] = v.y;
      As[c4 * 4 + 2][r] = v.z;
      As[c4 * 4 + 3][r] = v.w;
    }
#pragma unroll
    for (int i = 0; i < 10; i++) {
      int id = t + i * 128;
      int r = id / C_OUT, c = id % C_OUT;
      Bs[r][c] = __ldg(W + (size_t)(k0 + r) * C_OUT + c);
    }
    __syncthreads();

#pragma unroll
    for (int kk = 0; kk < G2_BK / 8; kk++) {
      uint32_t a[4];
      a[0] = f2tf32(As[kk * 8 + tg    ][m_base + g    ]);
      a[1] = f2tf32(As[kk * 8 + tg    ][m_base + g + 8]);
      a[2] = f2tf32(As[kk * 8 + tg + 4][m_base + g    ]);
      a[3] = f2tf32(As[kk * 8 + tg + 4][m_base + g + 8]);
#pragma unroll
      for (int nt = 0; nt < 5; nt++) {
        uint32_t b[2];
        b[0] = f2tf32(Bs[kk * 8 + tg    ][nt * 8 + g]);
        b[1] = f2tf32(Bs[kk * 8 + tg + 4][nt * 8 + g]);
        mma_tf32(acc[nt], a, b, acc[nt]);
      }
    }
    __syncthreads();
  }

  int r1 = row0 + m_base + g;
  int r2 = r1 + 8;
#pragma unroll
  for (int nt = 0; nt < 5; nt++) {
    int col = nt * 8 + tg * 2;
    if (r1 < M) *(__half2*)(g_h2 + (size_t)r1 * C_OUT + col) =
        __floats2half2_rn(acc[nt][0], acc[nt][1]);
    if (r2 < M) *(__half2*)(g_h2 + (size_t)r2 * C_OUT + col) =
        __floats2half2_rn(acc[nt][2], acc[nt][3]);
  }
}

// ---------------------------------------------------------------------------
// agg2 + bias + log_softmax, fused. One warp per dst row; fp16 gather.
// ---------------------------------------------------------------------------
__global__ __launch_bounds__(256) void agg2_kernel(
    const float* __restrict__ b2, float* __restrict__ out, int M) {
  int row = blockIdx.x * 8 + (threadIdx.x >> 5);
  if (row >= M) return;
  int lane = threadIdx.x & 31;
  const bool has2 = lane < 8;
  int beg = g_rowptr[row];
  int end = g_rowptr[row + 1];

  float a0 = __ldg(b2 + lane);
  float a1 = has2 ? __ldg(b2 + lane + 32) : 0.f;

  int e = beg;
  for (; e + 4 <= end; e += 4) {
    uint2 c0 = g_csr[e],     c1 = g_csr[e + 1];
    uint2 c2 = g_csr[e + 2], c3 = g_csr[e + 3];
    float w0 = __uint_as_float(c0.y), w1 = __uint_as_float(c1.y);
    float w2 = __uint_as_float(c2.y), w3 = __uint_as_float(c3.y);
    const __half* p0 = g_h2 + (size_t)c0.x * C_OUT;
    const __half* p1 = g_h2 + (size_t)c1.x * C_OUT;
    const __half* p2 = g_h2 + (size_t)c2.x * C_OUT;
    const __half* p3 = g_h2 + (size_t)c3.x * C_OUT;
    float u0 = __half2float(p0[lane]);
    float u1 = __half2float(p1[lane]);
    float u2 = __half2float(p2[lane]);
    float u3 = __half2float(p3[lane]);
    a0 += w0 * u0 + w1 * u1 + w2 * u2 + w3 * u3;
    if (has2) {
      a1 += w0 * __half2float(p0[lane + 32]) + w1 * __half2float(p1[lane + 32])
          + w2 * __half2float(p2[lane + 32]) + w3 * __half2float(p3[lane + 32]);
    }
  }
  for (; e < end; e++) {
    uint2 c0 = g_csr[e];
    float w0 = __uint_as_float(c0.y);
    const __half* p0 = g_h2 + (size_t)c0.x * C_OUT;
    a0 += w0 * __half2float(p0[lane]);
    if (has2) a1 += w0 * __half2float(p0[lane + 32]);
  }

  float m = has2 ? fmaxf(a0, a1) : a0;
#pragma unroll
  for (int o = 16; o; o >>= 1) m = fmaxf(m, __shfl_xor_sync(0xffffffffu, m, o));
  float s = expf(a0 - m) + (has2 ? expf(a1 - m) : 0.f);
#pragma unroll
  for (int o = 16; o; o >>= 1) s += __shfl_xor_sync(0xffffffffu, s, o);
  float lse = m + logf(s);

  float* p = out + (size_t)row * C_OUT;
  p[lane] = a0 - lse;
  if (has2) p[lane + 32] = a1 - lse;
}

// ---------------------------------------------------------------------------
extern "C" void kernel_launch(void* const* d_in, const int* in_sizes, int n_in,
                              void* d_out, int out_size) {
  const float* x  = (const float*)d_in[0];
  const int*   ei = (const int*)d_in[1];   // int32
  const float* ew = (const float*)d_in[2];
  const float* W1 = (const float*)d_in[3];
  const float* b1 = (const float*)d_in[4];
  const float* W2 = (const float*)d_in[5];
  const float* b2 = (const float*)d_in[6];
  float* out      = (float*)d_out;

  const int M = in_sizes[0] / F_IN;
  const int E = in_sizes[2];
  const int nblk = (M + SCAN_BLK - 1) / SCAN_BLK;

  gemm1_kernel<<<(M + 127) / 128, 256>>>(x, W1, M);

  // CSR build
  zero_cnt_kernel<<<(M + 255) / 256, 256>>>(M);
  hist_kernel<<<(E + 255) / 256, 256>>>(ei, E);
  scanA_kernel<<<nblk, SCAN_BLK>>>(M);
  scanB_kernel<<<1, SCAN_BLK>>>(nblk, M, E);
  scanC_kernel<<<nblk, SCAN_BLK>>>(M);
  fill_kernel<<<(E + 255) / 256, 256>>>(ei, ew, E);

  // Layer 1 aggregation (fp16 gather) + bias + ReLU
  agg1_kernel<<<(M + 7) / 8, 256>>>(b1, M);

  // GEMM2 (tf32 MMA, fp16 output)
  gemm2_kernel<<<(M + 63) / 64, 128>>>(W2, M);

  // Layer 2 aggregation + bias + log_softmax
  agg2_kernel<<<(M + 7) / 8, 256>>>(b2, out, M);
}